// round 10
// baseline (speedup 1.0000x reference)
#include <cuda_runtime.h>
#include <cuda_fp16.h>
#include <cuda_bf16.h>

// Problem constants (from reference: N=100000, F=128, Fo=64, E=1600000)
#define NMAX 100000
#define FDIM 128
#define FO   64

__device__ __align__(16) float  g_deg[NMAX];
__device__ __align__(16) __half g_hs [NMAX * FO];  // fp16 messages: h[i]*dinv[i]
__device__ __align__(16) float  g_tmp[NMAX * FO];  // fp32 aggregate (init = exact self loop)

// ---- packed f32x2 helpers (sm_103a) ---------------------------------------
__device__ __forceinline__ unsigned long long pk2(float s) {
    unsigned long long r;
    asm("mov.b64 %0, {%1, %1};" : "=l"(r) : "f"(s));
    return r;
}
__device__ __forceinline__ void fma2(unsigned long long& d,
                                     unsigned long long a,
                                     unsigned long long b) {
    asm("fma.rn.f32x2 %0, %1, %2, %0;" : "+l"(d) : "l"(a), "l"(b));
}
__device__ __forceinline__ float2 unpk2(unsigned long long v) {
    float2 f;
    asm("mov.b64 {%0, %1}, %2;" : "=f"(f.x), "=f"(f.y) : "l"(v));
    return f;
}

// ---------------------------------------------------------------------------
__global__ void k_deg_init(int N) {
    int i = blockIdx.x * blockDim.x + threadIdx.x;
    if (i < N) g_deg[i] = 1.0f;
}

__global__ void k_deg_acc(const int* __restrict__ ei, int E) {
    int t = blockIdx.x * blockDim.x + threadIdx.x;
    int e0 = t * 4;
    if (e0 + 3 < E) {
        int4 d = *(const int4*)(ei + E + e0);
        atomicAdd(&g_deg[d.x], 1.0f);
        atomicAdd(&g_deg[d.y], 1.0f);
        atomicAdd(&g_deg[d.z], 1.0f);
        atomicAdd(&g_deg[d.w], 1.0f);
    } else {
        for (int e = e0; e < E; e++) atomicAdd(&g_deg[ei[E + e]], 1.0f);
    }
}

// ---------------------------------------------------------------------------
// K2: hs(fp16) = (x @ W^T) * dinv ; tmp(fp32) = same (exact self-loop init)
// R7 config (best measured): 128 threads, 128 rows/block, thread = 8x8.
#define GROWS 128
#define XGRP(k, g)  ((((g) + (k)) & 31) * 4)

__global__ __launch_bounds__(128) void k_gemm(const float* __restrict__ x,
                                              const float* __restrict__ W,
                                              int N) {
    extern __shared__ float smem[];
    float* W_sh = smem;                 // [k*64 + c] = W[c*128 + k]   (32KB)
    float* x_sh = smem + FDIM * FO;     // [k*128 + swizzle(r)]        (64KB)

    int tid = threadIdx.x;
    int row0 = blockIdx.x * GROWS;

    #pragma unroll
    for (int i = tid; i < FO * FDIM; i += 128) {
        int c = i >> 7;
        int k = i & 127;
        W_sh[k * FO + c] = W[i];
    }

    #pragma unroll
    for (int i = tid; i < GROWS * FDIM; i += 128) {
        int r = i >> 7;
        int k = i & 127;
        int gr = row0 + r;
        float v = (gr < N) ? x[(long)gr * FDIM + k] : 0.0f;
        x_sh[k * GROWS + XGRP(k, r >> 2) + (r & 3)] = v;
    }
    __syncthreads();

    int rg = tid >> 3;          // 0..15 -> rows rg*8 .. rg*8+7
    int c0 = (tid & 7) << 3;    // 0,8,...,56

    unsigned long long acc[8][4];
    #pragma unroll
    for (int i = 0; i < 8; i++)
        #pragma unroll
        for (int j = 0; j < 4; j++) acc[i][j] = 0ull;

    #pragma unroll 4
    for (int k = 0; k < FDIM; k++) {
        float4 xa = *(const float4*)&x_sh[k * GROWS + XGRP(k, rg * 2)];
        float4 xb = *(const float4*)&x_sh[k * GROWS + XGRP(k, rg * 2 + 1)];
        ulonglong2 w01 = *(const ulonglong2*)&W_sh[k * FO + c0];
        ulonglong2 w23 = *(const ulonglong2*)&W_sh[k * FO + c0 + 4];
        float xs[8] = {xa.x, xa.y, xa.z, xa.w, xb.x, xb.y, xb.z, xb.w};
        #pragma unroll
        for (int i = 0; i < 8; i++) {
            unsigned long long p = pk2(xs[i]);
            fma2(acc[i][0], p, w01.x);
            fma2(acc[i][1], p, w01.y);
            fma2(acc[i][2], p, w23.x);
            fma2(acc[i][3], p, w23.y);
        }
    }

    #pragma unroll
    for (int i = 0; i < 8; i++) {
        int gr = row0 + rg * 8 + i;
        if (gr >= N) continue;
        float dinv = rsqrtf(g_deg[gr]);
        float2 p0 = unpk2(acc[i][0]), p1 = unpk2(acc[i][1]);
        float2 p2 = unpk2(acc[i][2]), p3 = unpk2(acc[i][3]);
        float4 v0 = make_float4(p0.x * dinv, p0.y * dinv, p1.x * dinv, p1.y * dinv);
        float4 v1 = make_float4(p2.x * dinv, p2.y * dinv, p3.x * dinv, p3.y * dinv);
        long base = (long)gr * FO + c0;
        // exact fp32 self-loop contribution
        *(float4*)&g_tmp[base]     = v0;
        *(float4*)&g_tmp[base + 4] = v1;
        // fp16 message copy (8 halves = 16B)
        __half2 hh[4];
        hh[0] = __floats2half2_rn(v0.x, v0.y);
        hh[1] = __floats2half2_rn(v0.z, v0.w);
        hh[2] = __floats2half2_rn(v1.x, v1.y);
        hh[3] = __floats2half2_rn(v1.z, v1.w);
        *(uint4*)&g_hs[base] = *(const uint4*)hh;
    }
}

// ---------------------------------------------------------------------------
// K3: scatter-add: tmp[dst] += hs[src]  — warp per edge.
// Gather: one LDG.32 of half2 per edge (32 lanes x 4B = ONE 128B line).
// Accumulate: fp32 RED.v2 (2 lines). LTS bytes/edge: 384 vs 512 before.
__global__ __launch_bounds__(256) void k_scatter(const int* __restrict__ ei, int E) {
    int warp = (int)((blockIdx.x * blockDim.x + threadIdx.x) >> 5);
    int lane = threadIdx.x & 31;
    int e0 = warp << 5;
    if (e0 >= E) return;
    int n = E - e0; if (n > 32) n = 32;

    int mysrc = 0, mydst = 0;
    if (lane < n) {
        mysrc = __ldg(ei + e0 + lane);
        mydst = __ldg(ei + E + e0 + lane);
    }

    int j = lane << 1;   // half/float index 0,2,...,62
    #pragma unroll 4
    for (int i = 0; i < n; i++) {
        int src = __shfl_sync(0xFFFFFFFFu, mysrc, i);
        int dst = __shfl_sync(0xFFFFFFFFu, mydst, i);
        __half2 hv = __ldg((const __half2*)(g_hs + (long)src * FO) + lane);
        float2 v = __half22float2(hv);
        float* p = g_tmp + (long)dst * FO + j;
        asm volatile("red.global.add.v2.f32 [%0], {%1, %2};"
                     :: "l"(p), "f"(v.x), "f"(v.y) : "memory");
    }
}

// ---------------------------------------------------------------------------
// K4: out = sigmoid( relu(dinv*tmp + b_conv) . W_lin + b_lin )  — warp per node
__global__ void k_final(const float* __restrict__ Wl,
                        const float* __restrict__ bl,
                        const float* __restrict__ bconv,
                        float* __restrict__ out, int N) {
    int warp = (int)((blockIdx.x * blockDim.x + threadIdx.x) >> 5);
    int lane = threadIdx.x & 31;
    if (warp >= N) return;

    float dinv = rsqrtf(g_deg[warp]);
    float2 tv = *(const float2*)&g_tmp[(long)warp * FO + lane * 2];
    float2 wv = *(const float2*)&Wl[lane * 2];
    float2 bc = *(const float2*)&bconv[lane * 2];

    float v0 = fmaxf(fmaf(tv.x, dinv, bc.x), 0.0f);
    float v1 = fmaxf(fmaf(tv.y, dinv, bc.y), 0.0f);
    float s  = v0 * wv.x + v1 * wv.y;

    #pragma unroll
    for (int o = 16; o; o >>= 1) s += __shfl_xor_sync(0xFFFFFFFFu, s, o);

    if (lane == 0) {
        float z = s + bl[0];
        out[warp] = 1.0f / (1.0f + expf(-z));
    }
}

// ---------------------------------------------------------------------------
extern "C" void kernel_launch(void* const* d_in, const int* in_sizes, int n_in,
                              void* d_out, int out_size) {
    const float* x     = (const float*)d_in[0];
    const int*   ei    = (const int*)  d_in[1];
    const float* Wc    = (const float*)d_in[2];
    const float* bc    = (const float*)d_in[3];
    const float* Wl    = (const float*)d_in[4];
    const float* bl    = (const float*)d_in[5];
    float*       out   = (float*)d_out;

    int N = in_sizes[0] / FDIM;
    int E = in_sizes[1] / 2;
    if (N > NMAX) N = NMAX;

    const int GEMM_SMEM = (FDIM * FO + GROWS * FDIM) * (int)sizeof(float); // 96KB
    cudaFuncSetAttribute(k_gemm, cudaFuncAttributeMaxDynamicSharedMemorySize,
                         GEMM_SMEM);

    k_deg_init<<<(N + 255) / 256, 256>>>(N);
    k_deg_acc <<<((E + 3) / 4 + 255) / 256, 256>>>(ei, E);
    k_gemm    <<<(N + GROWS - 1) / GROWS, 128, GEMM_SMEM>>>(x, Wc, N);
    {
        int nwarp  = (E + 31) / 32;
        int blocks = (nwarp + 7) / 8;
        k_scatter<<<blocks, 256>>>(ei, E);
    }
    k_final<<<(N + 7) / 8, 256>>>(Wl, bl, bc, out, N);
}

// round 11
// speedup vs baseline: 1.2829x; 1.2829x over previous
#include <cuda_runtime.h>
#include <cuda_fp16.h>
#include <cuda_bf16.h>

// Problem constants (from reference: N=100000, F=128, Fo=64, E=1600000)
#define NMAX 100000
#define FDIM 128
#define FO   64

__device__ __align__(16) float  g_deg[NMAX];
__device__ __align__(16) __half g_hs [NMAX * FO];  // fp16 messages: h[i]*dinv[i]
__device__ __align__(16) __half g_tmp[NMAX * FO];  // fp16 aggregate (init = self loop)

// ---- packed f32x2 helpers (sm_103a) ---------------------------------------
__device__ __forceinline__ unsigned long long pk2(float s) {
    unsigned long long r;
    asm("mov.b64 %0, {%1, %1};" : "=l"(r) : "f"(s));
    return r;
}
__device__ __forceinline__ void fma2(unsigned long long& d,
                                     unsigned long long a,
                                     unsigned long long b) {
    asm("fma.rn.f32x2 %0, %1, %2, %0;" : "+l"(d) : "l"(a), "l"(b));
}
__device__ __forceinline__ float2 unpk2(unsigned long long v) {
    float2 f;
    asm("mov.b64 {%0, %1}, %2;" : "=f"(f.x), "=f"(f.y) : "l"(v));
    return f;
}

// ---------------------------------------------------------------------------
__global__ void k_deg_init(int N) {
    int i = blockIdx.x * blockDim.x + threadIdx.x;
    if (i < N) g_deg[i] = 1.0f;
}

__global__ void k_deg_acc(const int* __restrict__ ei, int E) {
    int t = blockIdx.x * blockDim.x + threadIdx.x;
    int e0 = t * 4;
    if (e0 + 3 < E) {
        int4 d = *(const int4*)(ei + E + e0);
        atomicAdd(&g_deg[d.x], 1.0f);
        atomicAdd(&g_deg[d.y], 1.0f);
        atomicAdd(&g_deg[d.z], 1.0f);
        atomicAdd(&g_deg[d.w], 1.0f);
    } else {
        for (int e = e0; e < E; e++) atomicAdd(&g_deg[ei[E + e]], 1.0f);
    }
}

// ---------------------------------------------------------------------------
// K2: hs(fp16) = (x @ W^T) * dinv ; tmp(fp16) = same (self-loop init)
// R7 config (best measured): 128 threads, 128 rows/block, thread = 8x8.
#define GROWS 128
#define XGRP(k, g)  ((((g) + (k)) & 31) * 4)

__global__ __launch_bounds__(128) void k_gemm(const float* __restrict__ x,
                                              const float* __restrict__ W,
                                              int N) {
    extern __shared__ float smem[];
    float* W_sh = smem;                 // [k*64 + c] = W[c*128 + k]   (32KB)
    float* x_sh = smem + FDIM * FO;     // [k*128 + swizzle(r)]        (64KB)

    int tid = threadIdx.x;
    int row0 = blockIdx.x * GROWS;

    #pragma unroll
    for (int i = tid; i < FO * FDIM; i += 128) {
        int c = i >> 7;
        int k = i & 127;
        W_sh[k * FO + c] = W[i];
    }

    #pragma unroll
    for (int i = tid; i < GROWS * FDIM; i += 128) {
        int r = i >> 7;
        int k = i & 127;
        int gr = row0 + r;
        float v = (gr < N) ? x[(long)gr * FDIM + k] : 0.0f;
        x_sh[k * GROWS + XGRP(k, r >> 2) + (r & 3)] = v;
    }
    __syncthreads();

    int rg = tid >> 3;          // 0..15 -> rows rg*8 .. rg*8+7
    int c0 = (tid & 7) << 3;    // 0,8,...,56

    unsigned long long acc[8][4];
    #pragma unroll
    for (int i = 0; i < 8; i++)
        #pragma unroll
        for (int j = 0; j < 4; j++) acc[i][j] = 0ull;

    #pragma unroll 4
    for (int k = 0; k < FDIM; k++) {
        float4 xa = *(const float4*)&x_sh[k * GROWS + XGRP(k, rg * 2)];
        float4 xb = *(const float4*)&x_sh[k * GROWS + XGRP(k, rg * 2 + 1)];
        ulonglong2 w01 = *(const ulonglong2*)&W_sh[k * FO + c0];
        ulonglong2 w23 = *(const ulonglong2*)&W_sh[k * FO + c0 + 4];
        float xs[8] = {xa.x, xa.y, xa.z, xa.w, xb.x, xb.y, xb.z, xb.w};
        #pragma unroll
        for (int i = 0; i < 8; i++) {
            unsigned long long p = pk2(xs[i]);
            fma2(acc[i][0], p, w01.x);
            fma2(acc[i][1], p, w01.y);
            fma2(acc[i][2], p, w23.x);
            fma2(acc[i][3], p, w23.y);
        }
    }

    #pragma unroll
    for (int i = 0; i < 8; i++) {
        int gr = row0 + rg * 8 + i;
        if (gr >= N) continue;
        float dinv = rsqrtf(g_deg[gr]);
        float2 p0 = unpk2(acc[i][0]), p1 = unpk2(acc[i][1]);
        float2 p2 = unpk2(acc[i][2]), p3 = unpk2(acc[i][3]);
        __half2 hh[4];
        hh[0] = __floats2half2_rn(p0.x * dinv, p0.y * dinv);
        hh[1] = __floats2half2_rn(p1.x * dinv, p1.y * dinv);
        hh[2] = __floats2half2_rn(p2.x * dinv, p2.y * dinv);
        hh[3] = __floats2half2_rn(p3.x * dinv, p3.y * dinv);
        long base = (long)gr * FO + c0;
        *(uint4*)&g_hs [base] = *(const uint4*)hh;   // message copy
        *(uint4*)&g_tmp[base] = *(const uint4*)hh;   // self-loop init
    }
}

// ---------------------------------------------------------------------------
// K3: scatter-add: tmp[dst] += hs[src]  — warp per edge, fp16x2 end to end.
// Per edge: 1 LDG.32 (one 128B line) + 1 red.global.add.noftz.f16x2 (one
// 128B line). The gathered uint32 is RED'd directly — zero convert instrs.
__global__ __launch_bounds__(256) void k_scatter(const int* __restrict__ ei, int E) {
    int warp = (int)((blockIdx.x * blockDim.x + threadIdx.x) >> 5);
    int lane = threadIdx.x & 31;
    int e0 = warp << 5;
    if (e0 >= E) return;
    int n = E - e0; if (n > 32) n = 32;

    int mysrc = 0, mydst = 0;
    if (lane < n) {
        mysrc = __ldg(ei + e0 + lane);
        mydst = __ldg(ei + E + e0 + lane);
    }

    #pragma unroll 4
    for (int i = 0; i < n; i++) {
        int src = __shfl_sync(0xFFFFFFFFu, mysrc, i);
        int dst = __shfl_sync(0xFFFFFFFFu, mydst, i);
        unsigned hv = __ldg((const unsigned*)(g_hs + (long)src * FO) + lane);
        __half* p = g_tmp + (long)dst * FO + (lane << 1);
        asm volatile("red.global.add.noftz.f16x2 [%0], %1;"
                     :: "l"(p), "r"(hv) : "memory");
    }
}

// ---------------------------------------------------------------------------
// K4: out = sigmoid( relu(dinv*tmp + b_conv) . W_lin + b_lin )  — warp per node
__global__ void k_final(const float* __restrict__ Wl,
                        const float* __restrict__ bl,
                        const float* __restrict__ bconv,
                        float* __restrict__ out, int N) {
    int warp = (int)((blockIdx.x * blockDim.x + threadIdx.x) >> 5);
    int lane = threadIdx.x & 31;
    if (warp >= N) return;

    float dinv = rsqrtf(g_deg[warp]);
    __half2 th = *(const __half2*)&g_tmp[(long)warp * FO + lane * 2];
    float2 tv = __half22float2(th);
    float2 wv = *(const float2*)&Wl[lane * 2];
    float2 bc = *(const float2*)&bconv[lane * 2];

    float v0 = fmaxf(fmaf(tv.x, dinv, bc.x), 0.0f);
    float v1 = fmaxf(fmaf(tv.y, dinv, bc.y), 0.0f);
    float s  = v0 * wv.x + v1 * wv.y;

    #pragma unroll
    for (int o = 16; o; o >>= 1) s += __shfl_xor_sync(0xFFFFFFFFu, s, o);

    if (lane == 0) {
        float z = s + bl[0];
        out[warp] = 1.0f / (1.0f + expf(-z));
    }
}

// ---------------------------------------------------------------------------
extern "C" void kernel_launch(void* const* d_in, const int* in_sizes, int n_in,
                              void* d_out, int out_size) {
    const float* x     = (const float*)d_in[0];
    const int*   ei    = (const int*)  d_in[1];
    const float* Wc    = (const float*)d_in[2];
    const float* bc    = (const float*)d_in[3];
    const float* Wl    = (const float*)d_in[4];
    const float* bl    = (const float*)d_in[5];
    float*       out   = (float*)d_out;

    int N = in_sizes[0] / FDIM;
    int E = in_sizes[1] / 2;
    if (N > NMAX) N = NMAX;

    const int GEMM_SMEM = (FDIM * FO + GROWS * FDIM) * (int)sizeof(float); // 96KB
    cudaFuncSetAttribute(k_gemm, cudaFuncAttributeMaxDynamicSharedMemorySize,
                         GEMM_SMEM);

    k_deg_init<<<(N + 255) / 256, 256>>>(N);
    k_deg_acc <<<((E + 3) / 4 + 255) / 256, 256>>>(ei, E);
    k_gemm    <<<(N + GROWS - 1) / GROWS, 128, GEMM_SMEM>>>(x, Wc, N);
    {
        int nwarp  = (E + 31) / 32;
        int blocks = (nwarp + 7) / 8;
        k_scatter<<<blocks, 256>>>(ei, E);
    }
    k_final<<<(N + 7) / 8, 256>>>(Wl, bl, bc, out, N);
}

// round 12
// speedup vs baseline: 1.4527x; 1.1323x over previous
#include <cuda_runtime.h>
#include <cuda_fp16.h>
#include <cuda_bf16.h>

// Problem constants (from reference: N=100000, F=128, Fo=64, E=1600000)
#define NMAX 100000
#define FDIM 128
#define FO   64

__device__ __align__(16) float  g_deg[NMAX];
__device__ __align__(16) __half g_hs [NMAX * FO];  // fp16 messages: h[i]*dinv[i]
__device__ __align__(16) __half g_tmp[NMAX * FO];  // fp16 aggregate (init = self loop)

// ---------------------------------------------------------------------------
__global__ void k_deg_init(int N) {
    int i = blockIdx.x * blockDim.x + threadIdx.x;
    if (i < N) g_deg[i] = 1.0f;
}

__global__ void k_deg_acc(const int* __restrict__ ei, int E) {
    int t = blockIdx.x * blockDim.x + threadIdx.x;
    int e0 = t * 4;
    if (e0 + 3 < E) {
        int4 d = *(const int4*)(ei + E + e0);
        atomicAdd(&g_deg[d.x], 1.0f);
        atomicAdd(&g_deg[d.y], 1.0f);
        atomicAdd(&g_deg[d.z], 1.0f);
        atomicAdd(&g_deg[d.w], 1.0f);
    } else {
        for (int e = e0; e < E; e++) atomicAdd(&g_deg[ei[E + e]], 1.0f);
    }
}

// ---------------------------------------------------------------------------
// K2: hs/tmp (fp16) = (x @ W^T) * dinv  via HMMA mma.sync m16n8k16 f32.f16.
// 256 threads (8 warps), 128-row M-tile. Warp w owns rows w*16..w*16+15.
// Smem fp16 with 136-half padded rows: all LDS.32 fragment loads and the
// fill STS.64s are bank-conflict-free (68 words/row -> bank offset 4/row).
#define SA 136                                  // padded row stride (halves)

__global__ __launch_bounds__(256) void k_gemm(const float* __restrict__ x,
                                              const float* __restrict__ W,
                                              int N) {
    extern __shared__ __half smh[];
    __half* A_sh = smh;                 // [128][SA]
    __half* B_sh = smh + 128 * SA;      // [64][SA]  (W as [n][k])

    int tid = threadIdx.x;
    int row0 = blockIdx.x * 128;

    // W -> B_sh (fp32 -> fp16), 64 rows x 32 float4
    #pragma unroll
    for (int i = tid; i < 64 * 32; i += 256) {
        int n  = i >> 5;
        int k4 = (i & 31) << 2;
        float4 v = *(const float4*)(W + n * FDIM + k4);
        __half* p = B_sh + n * SA + k4;
        *(__half2*)(p)     = __floats2half2_rn(v.x, v.y);
        *(__half2*)(p + 2) = __floats2half2_rn(v.z, v.w);
    }

    // x -> A_sh (fp32 -> fp16), 128 rows x 32 float4, coalesced
    #pragma unroll
    for (int i = tid; i < 128 * 32; i += 256) {
        int r  = i >> 5;
        int k4 = (i & 31) << 2;
        int gr = row0 + r;
        float4 v = (gr < N) ? *(const float4*)(x + (long)gr * FDIM + k4)
                            : make_float4(0.f, 0.f, 0.f, 0.f);
        __half* p = A_sh + r * SA + k4;
        *(__half2*)(p)     = __floats2half2_rn(v.x, v.y);
        *(__half2*)(p + 2) = __floats2half2_rn(v.z, v.w);
    }
    __syncthreads();

    int warp = tid >> 5;
    int lane = tid & 31;
    int gid  = lane >> 2;       // 0..7
    int tig  = lane & 3;        // 0..3
    int mrow = warp * 16;

    float acc[8][4];
    #pragma unroll
    for (int nt = 0; nt < 8; nt++)
        #pragma unroll
        for (int j = 0; j < 4; j++) acc[nt][j] = 0.f;

    #pragma unroll
    for (int kt = 0; kt < 8; kt++) {
        int kb = kt * 16 + tig * 2;
        const __half* ar0 = A_sh + (mrow + gid) * SA + kb;
        const __half* ar1 = ar0 + 8 * SA;
        unsigned a0 = *(const unsigned*)(ar0);
        unsigned a1 = *(const unsigned*)(ar1);
        unsigned a2 = *(const unsigned*)(ar0 + 8);
        unsigned a3 = *(const unsigned*)(ar1 + 8);
        #pragma unroll
        for (int nt = 0; nt < 8; nt++) {
            const __half* br = B_sh + (nt * 8 + gid) * SA + kb;
            unsigned b0 = *(const unsigned*)(br);
            unsigned b1 = *(const unsigned*)(br + 8);
            asm("mma.sync.aligned.m16n8k16.row.col.f32.f16.f16.f32 "
                "{%0,%1,%2,%3}, {%4,%5,%6,%7}, {%8,%9}, {%0,%1,%2,%3};"
                : "+f"(acc[nt][0]), "+f"(acc[nt][1]),
                  "+f"(acc[nt][2]), "+f"(acc[nt][3])
                : "r"(a0), "r"(a1), "r"(a2), "r"(a3), "r"(b0), "r"(b1));
        }
    }

    // Epilogue: rows r0 = row0+mrow+gid (acc[nt][0..1]), r1 = r0+8 ([2..3]).
    int r0 = row0 + mrow + gid;
    int r1 = r0 + 8;
    float dinv0 = (r0 < N) ? rsqrtf(g_deg[r0]) : 0.f;
    float dinv1 = (r1 < N) ? rsqrtf(g_deg[r1]) : 0.f;
    #pragma unroll
    for (int nt = 0; nt < 8; nt++) {
        int c = nt * 8 + tig * 2;
        if (r0 < N) {
            __half2 h = __floats2half2_rn(acc[nt][0] * dinv0, acc[nt][1] * dinv0);
            long b = (long)r0 * FO + c;
            *(__half2*)(g_hs + b) = h;
            *(__half2*)(g_tmp + b) = h;
        }
        if (r1 < N) {
            __half2 h = __floats2half2_rn(acc[nt][2] * dinv1, acc[nt][3] * dinv1);
            long b = (long)r1 * FO + c;
            *(__half2*)(g_hs + b) = h;
            *(__half2*)(g_tmp + b) = h;
        }
    }
}

// ---------------------------------------------------------------------------
// K3: scatter-add: tmp[dst] += hs[src]  — warp per edge, fp16x2 end to end.
__global__ __launch_bounds__(256) void k_scatter(const int* __restrict__ ei, int E) {
    int warp = (int)((blockIdx.x * blockDim.x + threadIdx.x) >> 5);
    int lane = threadIdx.x & 31;
    int e0 = warp << 5;
    if (e0 >= E) return;
    int n = E - e0; if (n > 32) n = 32;

    int mysrc = 0, mydst = 0;
    if (lane < n) {
        mysrc = __ldg(ei + e0 + lane);
        mydst = __ldg(ei + E + e0 + lane);
    }

    #pragma unroll 4
    for (int i = 0; i < n; i++) {
        int src = __shfl_sync(0xFFFFFFFFu, mysrc, i);
        int dst = __shfl_sync(0xFFFFFFFFu, mydst, i);
        unsigned hv = __ldg((const unsigned*)(g_hs + (long)src * FO) + lane);
        __half* p = g_tmp + (long)dst * FO + (lane << 1);
        asm volatile("red.global.add.noftz.f16x2 [%0], %1;"
                     :: "l"(p), "r"(hv) : "memory");
    }
}

// ---------------------------------------------------------------------------
// K4: out = sigmoid( relu(dinv*tmp + b_conv) . W_lin + b_lin )  — warp per node
__global__ void k_final(const float* __restrict__ Wl,
                        const float* __restrict__ bl,
                        const float* __restrict__ bconv,
                        float* __restrict__ out, int N) {
    int warp = (int)((blockIdx.x * blockDim.x + threadIdx.x) >> 5);
    int lane = threadIdx.x & 31;
    if (warp >= N) return;

    float dinv = rsqrtf(g_deg[warp]);
    __half2 th = *(const __half2*)&g_tmp[(long)warp * FO + lane * 2];
    float2 tv = __half22float2(th);
    float2 wv = *(const float2*)&Wl[lane * 2];
    float2 bc = *(const float2*)&bconv[lane * 2];

    float v0 = fmaxf(fmaf(tv.x, dinv, bc.x), 0.0f);
    float v1 = fmaxf(fmaf(tv.y, dinv, bc.y), 0.0f);
    float s  = v0 * wv.x + v1 * wv.y;

    #pragma unroll
    for (int o = 16; o; o >>= 1) s += __shfl_xor_sync(0xFFFFFFFFu, s, o);

    if (lane == 0) {
        float z = s + bl[0];
        out[warp] = 1.0f / (1.0f + expf(-z));
    }
}

// ---------------------------------------------------------------------------
extern "C" void kernel_launch(void* const* d_in, const int* in_sizes, int n_in,
                              void* d_out, int out_size) {
    const float* x     = (const float*)d_in[0];
    const int*   ei    = (const int*)  d_in[1];
    const float* Wc    = (const float*)d_in[2];
    const float* bc    = (const float*)d_in[3];
    const float* Wl    = (const float*)d_in[4];
    const float* bl    = (const float*)d_in[5];
    float*       out   = (float*)d_out;

    int N = in_sizes[0] / FDIM;
    int E = in_sizes[1] / 2;
    if (N > NMAX) N = NMAX;

    const int GEMM_SMEM = (128 + 64) * SA * (int)sizeof(__half);   // 52224 B
    cudaFuncSetAttribute(k_gemm, cudaFuncAttributeMaxDynamicSharedMemorySize,
                         GEMM_SMEM);

    k_deg_init<<<(N + 255) / 256, 256>>>(N);
    k_deg_acc <<<((E + 3) / 4 + 255) / 256, 256>>>(ei, E);
    k_gemm    <<<(N + 127) / 128, 256, GEMM_SMEM>>>(x, Wc, N);
    {
        int nwarp  = (E + 31) / 32;
        int blocks = (nwarp + 7) / 8;
        k_scatter<<<blocks, 256>>>(ei, E);
    }
    k_final<<<(N + 7) / 8, 256>>>(Wl, bl, bc, out, N);
}

// round 13
// speedup vs baseline: 2.1739x; 1.4965x over previous
#include <cuda_runtime.h>
#include <cuda_fp16.h>
#include <cuda_bf16.h>

// Problem constants (from reference: N=100000, F=128, Fo=64, E=1600000)
#define NMAX 100000
#define FDIM 128
#define FO   64

__device__ __align__(16) float  g_deg[NMAX];
__device__ __align__(16) __half g_hs [NMAX * FO];  // fp16 messages: h[i]*dinv[i]
__device__ __align__(16) __half g_tmp[NMAX * FO];  // fp16 aggregate (init = self loop)

// ---------------------------------------------------------------------------
__global__ void k_deg_init(int N) {
    int i = blockIdx.x * blockDim.x + threadIdx.x;
    if (i < N) g_deg[i] = 1.0f;
}

__global__ void k_deg_acc(const int* __restrict__ ei, int E) {
    int t = blockIdx.x * blockDim.x + threadIdx.x;
    int e0 = t * 4;
    if (e0 + 3 < E) {
        int4 d = *(const int4*)(ei + E + e0);
        atomicAdd(&g_deg[d.x], 1.0f);
        atomicAdd(&g_deg[d.y], 1.0f);
        atomicAdd(&g_deg[d.z], 1.0f);
        atomicAdd(&g_deg[d.w], 1.0f);
    } else {
        for (int e = e0; e < E; e++) atomicAdd(&g_deg[ei[E + e]], 1.0f);
    }
}

// ---------------------------------------------------------------------------
// K2: hs/tmp (fp16) = (x @ W^T) * dinv  via HMMA mma.sync m16n8k16 f32.f16.
// (unchanged from R12 — measured good)
#define SA 136                                  // padded row stride (halves)

__global__ __launch_bounds__(256) void k_gemm(const float* __restrict__ x,
                                              const float* __restrict__ W,
                                              int N) {
    extern __shared__ __half smh[];
    __half* A_sh = smh;                 // [128][SA]
    __half* B_sh = smh + 128 * SA;      // [64][SA]  (W as [n][k])

    int tid = threadIdx.x;
    int row0 = blockIdx.x * 128;

    #pragma unroll
    for (int i = tid; i < 64 * 32; i += 256) {
        int n  = i >> 5;
        int k4 = (i & 31) << 2;
        float4 v = *(const float4*)(W + n * FDIM + k4);
        __half* p = B_sh + n * SA + k4;
        *(__half2*)(p)     = __floats2half2_rn(v.x, v.y);
        *(__half2*)(p + 2) = __floats2half2_rn(v.z, v.w);
    }

    #pragma unroll
    for (int i = tid; i < 128 * 32; i += 256) {
        int r  = i >> 5;
        int k4 = (i & 31) << 2;
        int gr = row0 + r;
        float4 v = (gr < N) ? *(const float4*)(x + (long)gr * FDIM + k4)
                            : make_float4(0.f, 0.f, 0.f, 0.f);
        __half* p = A_sh + r * SA + k4;
        *(__half2*)(p)     = __floats2half2_rn(v.x, v.y);
        *(__half2*)(p + 2) = __floats2half2_rn(v.z, v.w);
    }
    __syncthreads();

    int warp = tid >> 5;
    int lane = tid & 31;
    int gid  = lane >> 2;       // 0..7
    int tig  = lane & 3;        // 0..3
    int mrow = warp * 16;

    float acc[8][4];
    #pragma unroll
    for (int nt = 0; nt < 8; nt++)
        #pragma unroll
        for (int j = 0; j < 4; j++) acc[nt][j] = 0.f;

    #pragma unroll
    for (int kt = 0; kt < 8; kt++) {
        int kb = kt * 16 + tig * 2;
        const __half* ar0 = A_sh + (mrow + gid) * SA + kb;
        const __half* ar1 = ar0 + 8 * SA;
        unsigned a0 = *(const unsigned*)(ar0);
        unsigned a1 = *(const unsigned*)(ar1);
        unsigned a2 = *(const unsigned*)(ar0 + 8);
        unsigned a3 = *(const unsigned*)(ar1 + 8);
        #pragma unroll
        for (int nt = 0; nt < 8; nt++) {
            const __half* br = B_sh + (nt * 8 + gid) * SA + kb;
            unsigned b0 = *(const unsigned*)(br);
            unsigned b1 = *(const unsigned*)(br + 8);
            asm("mma.sync.aligned.m16n8k16.row.col.f32.f16.f16.f32 "
                "{%0,%1,%2,%3}, {%4,%5,%6,%7}, {%8,%9}, {%0,%1,%2,%3};"
                : "+f"(acc[nt][0]), "+f"(acc[nt][1]),
                  "+f"(acc[nt][2]), "+f"(acc[nt][3])
                : "r"(a0), "r"(a1), "r"(a2), "r"(a3), "r"(b0), "r"(b1));
        }
    }

    int r0 = row0 + mrow + gid;
    int r1 = r0 + 8;
    float dinv0 = (r0 < N) ? rsqrtf(g_deg[r0]) : 0.f;
    float dinv1 = (r1 < N) ? rsqrtf(g_deg[r1]) : 0.f;
    #pragma unroll
    for (int nt = 0; nt < 8; nt++) {
        int c = nt * 8 + tig * 2;
        if (r0 < N) {
            __half2 h = __floats2half2_rn(acc[nt][0] * dinv0, acc[nt][1] * dinv0);
            long b = (long)r0 * FO + c;
            *(__half2*)(g_hs + b) = h;
            *(__half2*)(g_tmp + b) = h;
        }
        if (r1 < N) {
            __half2 h = __floats2half2_rn(acc[nt][2] * dinv1, acc[nt][3] * dinv1);
            long b = (long)r1 * FO + c;
            *(__half2*)(g_hs + b) = h;
            *(__half2*)(g_tmp + b) = h;
        }
    }
}

// ---------------------------------------------------------------------------
// K3: scatter-add: tmp[dst] += hs[src] — 4 EDGES PER WARP-ITERATION.
// lane -> (sub = lane>>3: which edge, li = lane&7: which 16B chunk of row).
// Gather: LDG.128 (8 lanes x 16B = one row/line per sub). Accumulate: ONE
// red.global.add.noftz.v4.f16x2 (16B/lane) covers all 4 edges -> 4x fewer
// RED instructions against the REDG->REDG structural floor (4 cyc).
// Duplicate dst rows within an instruction are safe: per-lane atomics commute.
__global__ __launch_bounds__(256) void k_scatter(const int* __restrict__ ei, int E) {
    int warp = (int)((blockIdx.x * blockDim.x + threadIdx.x) >> 5);
    int lane = threadIdx.x & 31;
    int e0 = warp << 5;
    if (e0 >= E) return;
    int n = E - e0; if (n > 32) n = 32;

    int mysrc = 0, mydst = 0;
    if (lane < n) {
        mysrc = __ldg(ei + e0 + lane);
        mydst = __ldg(ei + E + e0 + lane);
    }

    int sub = lane >> 3;    // 0..3
    int li  = lane & 7;     // 0..7

    int i = 0;
    #pragma unroll 2
    for (; i + 4 <= n; i += 4) {
        int src = __shfl_sync(0xFFFFFFFFu, mysrc, i + sub);
        int dst = __shfl_sync(0xFFFFFFFFu, mydst, i + sub);
        uint4 v = __ldg((const uint4*)(g_hs + (long)src * FO) + li);
        __half* p = g_tmp + (long)dst * FO + (li << 3);
        asm volatile("red.global.add.noftz.v4.f16x2 [%0], {%1, %2, %3, %4};"
                     :: "l"(p), "r"(v.x), "r"(v.y), "r"(v.z), "r"(v.w)
                     : "memory");
    }
    // remainder (<4 edges) — scalar f16x2 path, full warp per edge
    for (; i < n; i++) {
        int src = __shfl_sync(0xFFFFFFFFu, mysrc, i);
        int dst = __shfl_sync(0xFFFFFFFFu, mydst, i);
        unsigned hv = __ldg((const unsigned*)(g_hs + (long)src * FO) + lane);
        __half* p = g_tmp + (long)dst * FO + (lane << 1);
        asm volatile("red.global.add.noftz.f16x2 [%0], %1;"
                     :: "l"(p), "r"(hv) : "memory");
    }
}

// ---------------------------------------------------------------------------
// K4: out = sigmoid( relu(dinv*tmp + b_conv) . W_lin + b_lin )  — warp per node
__global__ void k_final(const float* __restrict__ Wl,
                        const float* __restrict__ bl,
                        const float* __restrict__ bconv,
                        float* __restrict__ out, int N) {
    int warp = (int)((blockIdx.x * blockDim.x + threadIdx.x) >> 5);
    int lane = threadIdx.x & 31;
    if (warp >= N) return;

    float dinv = rsqrtf(g_deg[warp]);
    __half2 th = *(const __half2*)&g_tmp[(long)warp * FO + lane * 2];
    float2 tv = __half22float2(th);
    float2 wv = *(const float2*)&Wl[lane * 2];
    float2 bc = *(const float2*)&bconv[lane * 2];

    float v0 = fmaxf(fmaf(tv.x, dinv, bc.x), 0.0f);
    float v1 = fmaxf(fmaf(tv.y, dinv, bc.y), 0.0f);
    float s  = v0 * wv.x + v1 * wv.y;

    #pragma unroll
    for (int o = 16; o; o >>= 1) s += __shfl_xor_sync(0xFFFFFFFFu, s, o);

    if (lane == 0) {
        float z = s + bl[0];
        out[warp] = 1.0f / (1.0f + expf(-z));
    }
}

// ---------------------------------------------------------------------------
extern "C" void kernel_launch(void* const* d_in, const int* in_sizes, int n_in,
                              void* d_out, int out_size) {
    const float* x     = (const float*)d_in[0];
    const int*   ei    = (const int*)  d_in[1];
    const float* Wc    = (const float*)d_in[2];
    const float* bc    = (const float*)d_in[3];
    const float* Wl    = (const float*)d_in[4];
    const float* bl    = (const float*)d_in[5];
    float*       out   = (float*)d_out;

    int N = in_sizes[0] / FDIM;
    int E = in_sizes[1] / 2;
    if (N > NMAX) N = NMAX;

    const int GEMM_SMEM = (128 + 64) * SA * (int)sizeof(__half);   // 52224 B
    cudaFuncSetAttribute(k_gemm, cudaFuncAttributeMaxDynamicSharedMemorySize,
                         GEMM_SMEM);

    k_deg_init<<<(N + 255) / 256, 256>>>(N);
    k_deg_acc <<<((E + 3) / 4 + 255) / 256, 256>>>(ei, E);
    k_gemm    <<<(N + 127) / 128, 256, GEMM_SMEM>>>(x, Wc, N);
    {
        int nwarp  = (E + 31) / 32;
        int blocks = (nwarp + 7) / 8;
        k_scatter<<<blocks, 256>>>(ei, E);
    }
    k_final<<<(N + 7) / 8, 256>>>(Wl, bl, bc, out, N);
}